// round 1
// baseline (speedup 1.0000x reference)
#include <cuda_runtime.h>
#include <math.h>

// Problem constants
#define B_SZ   256
#define T_SZ   64
#define IN_SZ  500
#define HID    512
#define G4     2048            // 4*HID
#define RAWN   16532           // 500*32 + 32 + 500
#define NA     500
#define NF     32

// ---------------- device scratch (static, no allocation) ----------------
__device__ float g_xg[(size_t)T_SZ * B_SZ * G4];      // 64*256*2048  (~128MB) input-transform + reused for layer1
__device__ float g_hseq[(size_t)T_SZ * B_SZ * HID];   // layer-0 hidden sequence (~32MB)
__device__ float g_hA[B_SZ * HID];
__device__ float g_hB[B_SZ * HID];
__device__ float g_c[B_SZ * HID];
__device__ float g_raw[(size_t)B_SZ * RAWN];          // FC output

__device__ __forceinline__ float sigmf(float x) { return 1.f / (1.f + expf(-x)); }

// ---------------- zero h/c ----------------
__global__ void zero_hc_kernel() {
    int i = blockIdx.x * 256 + threadIdx.x;   // grid 512 * 256 = 131072 = 256*512
    g_hA[i] = 0.f;
    g_c[i]  = 0.f;
}

// ---------------- generic GEMM: C = A @ B^T + bias1 (+ bias2) ----------------
// A: MxK row-major, B: NxK row-major (weights), C: MxN
// asel: 0 = external A, 1 = g_hseq, 2 = g_hA
// csel: 0 = g_xg, 1 = g_raw
// mode: 0 = direct rows, 1 = x-remap (row r = b*64+t -> out row t*256+b)
__global__ __launch_bounds__(256) void gemm_bias(
    const float* __restrict__ Aext, int asel,
    const float* __restrict__ B,
    const float* __restrict__ bias1, const float* __restrict__ bias2,
    int csel, int M, int N, int K, int mode)
{
    const float* A = (asel == 0) ? Aext : (asel == 1 ? g_hseq : g_hA);
    float* C = csel ? g_raw : g_xg;

    __shared__ float As[16][128];
    __shared__ float Bs[16][64];

    const int tid = threadIdx.x;
    const int tx = tid & 15;        // 0..15 -> 4 output cols
    const int ty = tid >> 4;        // 0..15 -> 8 output rows
    const int m0 = blockIdx.y * 128;
    const int n0 = blockIdx.x * 64;

    float acc[8][4];
#pragma unroll
    for (int r = 0; r < 8; r++)
#pragma unroll
        for (int cc = 0; cc < 4; cc++) acc[r][cc] = 0.f;

    const int kTiles = (K + 15) >> 4;
    for (int kt = 0; kt < kTiles; kt++) {
        const int k0 = kt << 4;
        // A tile: 128 rows x 16 k = 512 float4, 2 per thread
#pragma unroll
        for (int i = 0; i < 2; i++) {
            int idx = tid + i * 256;
            int row = idx >> 2;
            int kv = (idx & 3) << 2;
            float4 v = make_float4(0.f, 0.f, 0.f, 0.f);
            if (k0 + kv < K)
                v = *reinterpret_cast<const float4*>(&A[(size_t)(m0 + row) * K + k0 + kv]);
            As[kv + 0][row] = v.x; As[kv + 1][row] = v.y;
            As[kv + 2][row] = v.z; As[kv + 3][row] = v.w;
        }
        // B tile: 64 rows x 16 k = 256 float4, 1 per thread
        {
            int row = tid >> 2;
            int kv = (tid & 3) << 2;
            int wr = n0 + row;
            float4 v = make_float4(0.f, 0.f, 0.f, 0.f);
            if (wr < N && (k0 + kv) < K)
                v = *reinterpret_cast<const float4*>(&B[(size_t)wr * K + k0 + kv]);
            Bs[kv + 0][row] = v.x; Bs[kv + 1][row] = v.y;
            Bs[kv + 2][row] = v.z; Bs[kv + 3][row] = v.w;
        }
        __syncthreads();
#pragma unroll
        for (int k = 0; k < 16; k++) {
            float4 a0 = *reinterpret_cast<const float4*>(&As[k][ty * 8]);
            float4 a1 = *reinterpret_cast<const float4*>(&As[k][ty * 8 + 4]);
            float4 b0 = *reinterpret_cast<const float4*>(&Bs[k][tx * 4]);
            float av[8] = {a0.x, a0.y, a0.z, a0.w, a1.x, a1.y, a1.z, a1.w};
            float bv[4] = {b0.x, b0.y, b0.z, b0.w};
#pragma unroll
            for (int r = 0; r < 8; r++)
#pragma unroll
                for (int cc = 0; cc < 4; cc++)
                    acc[r][cc] = fmaf(av[r], bv[cc], acc[r][cc]);
        }
        __syncthreads();
    }

    const int colBase = n0 + tx * 4;
    if (colBase < N) {   // N % 4 == 0 for all uses -> float4-granular guard is exact
        float4 bv1 = *reinterpret_cast<const float4*>(&bias1[colBase]);
        float b1[4] = {bv1.x, bv1.y, bv1.z, bv1.w};
        if (bias2) {
            float4 bv2 = *reinterpret_cast<const float4*>(&bias2[colBase]);
            b1[0] += bv2.x; b1[1] += bv2.y; b1[2] += bv2.z; b1[3] += bv2.w;
        }
#pragma unroll
        for (int r = 0; r < 8; r++) {
            int row = m0 + ty * 8 + r;
            int orow = row;
            if (mode == 1) orow = (row & 63) * 256 + (row >> 6);  // [b][t] -> [t][b]
            float4 o;
            o.x = acc[r][0] + b1[0]; o.y = acc[r][1] + b1[1];
            o.z = acc[r][2] + b1[2]; o.w = acc[r][3] + b1[3];
            *reinterpret_cast<float4*>(&C[(size_t)orow * N + colBase]) = o;
        }
    }
}

// ---------------- fused LSTM step: gates GEMM + cell update ----------------
// Block: 64 batch rows x 16 hidden cols (all 4 gates). grid (512/16=32, 256/64=4).
// Gate columns interleaved in smem: col c = j*4 + q, so one thread (tx=j) gets all 4 gates.
__global__ __launch_bounds__(256) void lstm_step(
    int t, const float* __restrict__ w_hh, int layer)
{
    const float* xg   = g_xg + (size_t)t * B_SZ * G4;
    const float* h_in = (t & 1) ? g_hB : g_hA;
    float* h_out      = (t & 1) ? g_hA : g_hB;
    float* hseq       = (layer == 0) ? (g_hseq + (size_t)t * B_SZ * HID) : nullptr;

    __shared__ float As[16][64];   // [k][batch-local]
    __shared__ float Bs[16][64];   // [k][j*4+q]

    const int tid = threadIdx.x;
    const int tx = tid & 15;       // hidden unit j within tile
    const int ty = tid >> 4;       // 4 batch rows
    const int h0 = blockIdx.x * 16;
    const int m0 = blockIdx.y * 64;

    float acc[4][4];
#pragma unroll
    for (int r = 0; r < 4; r++)
#pragma unroll
        for (int q = 0; q < 4; q++) acc[r][q] = 0.f;

    for (int k0 = 0; k0 < HID; k0 += 16) {
        {   // A: 64 x 16 floats = 256 float4, 1 per thread
            int row = tid >> 2;
            int kv = (tid & 3) << 2;
            float4 v = *reinterpret_cast<const float4*>(&h_in[(m0 + row) * HID + k0 + kv]);
            As[kv + 0][row] = v.x; As[kv + 1][row] = v.y;
            As[kv + 2][row] = v.z; As[kv + 3][row] = v.w;
        }
        {   // B: 64 weight rows (16 hidden x 4 gates) x 16 k
            int cidx = tid >> 2;          // 0..63
            int kv = (tid & 3) << 2;
            int j = cidx >> 2, q = cidx & 3;
            int wr = q * HID + h0 + j;
            float4 v = *reinterpret_cast<const float4*>(&w_hh[(size_t)wr * HID + k0 + kv]);
            Bs[kv + 0][cidx] = v.x; Bs[kv + 1][cidx] = v.y;
            Bs[kv + 2][cidx] = v.z; Bs[kv + 3][cidx] = v.w;
        }
        __syncthreads();
#pragma unroll
        for (int k = 0; k < 16; k++) {
            float4 a = *reinterpret_cast<const float4*>(&As[k][ty * 4]);
            float4 b = *reinterpret_cast<const float4*>(&Bs[k][tx * 4]);
            float av[4] = {a.x, a.y, a.z, a.w};
            float bv[4] = {b.x, b.y, b.z, b.w};
#pragma unroll
            for (int r = 0; r < 4; r++)
#pragma unroll
                for (int q = 0; q < 4; q++)
                    acc[r][q] = fmaf(av[r], bv[q], acc[r][q]);
        }
        __syncthreads();
    }

    const int hx = h0 + tx;
#pragma unroll
    for (int r = 0; r < 4; r++) {
        int b = m0 + ty * 4 + r;
        const float* xgb = xg + (size_t)b * G4;
        float gi = acc[r][0] + xgb[hx];
        float gf = acc[r][1] + xgb[HID + hx];
        float gg = acc[r][2] + xgb[2 * HID + hx];
        float go = acc[r][3] + xgb[3 * HID + hx];
        int ci = b * HID + hx;
        float cn = sigmf(gf) * g_c[ci] + sigmf(gi) * tanhf(gg);
        float hn = sigmf(go) * tanhf(cn);
        g_c[ci] = cn;
        h_out[ci] = hn;
        if (hseq) hseq[ci] = hn;
    }
}

// ---------------- Sigma = (L*fv) @ L^T + diag(idio) ----------------
// grid (8,8,256): 64x64 output tile per block, K=32.
__global__ __launch_bounds__(256) void sigma_kernel(float* __restrict__ out)
{
    __shared__ float fvs[32];
    __shared__ float Ln[32][64];   // [f][n_local], pre-scaled by fv[f]
    __shared__ float Lm[32][64];   // [f][m_local]

    const int b  = blockIdx.z;
    const int n0 = blockIdx.y * 64;
    const int m0 = blockIdx.x * 64;
    const int tid = threadIdx.x;
    const int tx = tid & 15;
    const int ty = tid >> 4;
    const float* rb = g_raw + (size_t)b * RAWN;

    if (tid < 32) fvs[tid] = expf(rb[NA * NF + tid]);
    __syncthreads();

#pragma unroll
    for (int i = 0; i < 8; i++) {
        int idx = tid + i * 256;          // 0..2047
        int nl = idx >> 5, f = idx & 31;
        int n = n0 + nl;
        float v = (n < NA) ? rb[n * NF + f] : 0.f;
        Ln[f][nl] = v * fvs[f];
        int m = m0 + nl;
        float w = (m < NA) ? rb[m * NF + f] : 0.f;
        Lm[f][nl] = w;
    }
    __syncthreads();

    float acc[4][4];
#pragma unroll
    for (int r = 0; r < 4; r++)
#pragma unroll
        for (int cc = 0; cc < 4; cc++) acc[r][cc] = 0.f;

#pragma unroll
    for (int f = 0; f < 32; f++) {
        float4 a = *reinterpret_cast<const float4*>(&Ln[f][ty * 4]);
        float4 bb = *reinterpret_cast<const float4*>(&Lm[f][tx * 4]);
        float av[4] = {a.x, a.y, a.z, a.w};
        float bv[4] = {bb.x, bb.y, bb.z, bb.w};
#pragma unroll
        for (int r = 0; r < 4; r++)
#pragma unroll
            for (int cc = 0; cc < 4; cc++)
                acc[r][cc] = fmaf(av[r], bv[cc], acc[r][cc]);
    }

    const int mBase = m0 + tx * 4;
    if (mBase < NA) {   // NA % 4 == 0 -> exact float4 guard
#pragma unroll
        for (int r = 0; r < 4; r++) {
            int n = n0 + ty * 4 + r;
            if (n >= NA) continue;
            float o[4] = {acc[r][0], acc[r][1], acc[r][2], acc[r][3]};
            int d = n - mBase;
            if (d >= 0 && d < 4) o[d] += expf(rb[NA * NF + NF + n]);
            float4 ov = {o[0], o[1], o[2], o[3]};
            *reinterpret_cast<float4*>(&out[(size_t)b * NA * NA + (size_t)n * NA + mBase]) = ov;
        }
    }
}

// ---------------- launch ----------------
extern "C" void kernel_launch(void* const* d_in, const int* in_sizes, int n_in,
                              void* d_out, int out_size)
{
    const float* x     = (const float*)d_in[0];
    const float* w_ih0 = (const float*)d_in[1];
    const float* w_hh0 = (const float*)d_in[2];
    const float* b_ih0 = (const float*)d_in[3];
    const float* b_hh0 = (const float*)d_in[4];
    const float* w_ih1 = (const float*)d_in[5];
    const float* w_hh1 = (const float*)d_in[6];
    const float* b_ih1 = (const float*)d_in[7];
    const float* b_hh1 = (const float*)d_in[8];
    const float* fc_w  = (const float*)d_in[9];
    const float* fc_b  = (const float*)d_in[10];
    float* out = (float*)d_out;

    // -------- layer 0 --------
    zero_hc_kernel<<<512, 256>>>();
    // xg0[t][b][:] = x[b][t][:] @ w_ih0^T + b_ih0 + b_hh0   (row remap b*64+t -> t*256+b)
    gemm_bias<<<dim3(G4 / 64, (B_SZ * T_SZ) / 128), 256>>>(
        x, /*asel=*/0, w_ih0, b_ih0, b_hh0, /*csel=*/0,
        B_SZ * T_SZ, G4, IN_SZ, /*mode=*/1);
    for (int t = 0; t < T_SZ; t++)
        lstm_step<<<dim3(HID / 16, B_SZ / 64), 256>>>(t, w_hh0, /*layer=*/0);

    // -------- layer 1 --------
    zero_hc_kernel<<<512, 256>>>();
    // xg1[t][b][:] = hseq[t][b][:] @ w_ih1^T + b_ih1 + b_hh1
    gemm_bias<<<dim3(G4 / 64, (B_SZ * T_SZ) / 128), 256>>>(
        nullptr, /*asel=*/1, w_ih1, b_ih1, b_hh1, /*csel=*/0,
        B_SZ * T_SZ, G4, HID, /*mode=*/0);
    for (int t = 0; t < T_SZ; t++)
        lstm_step<<<dim3(HID / 16, B_SZ / 64), 256>>>(t, w_hh1, /*layer=*/1);
    // final h (t=63, odd) lives in g_hA

    // -------- FC: raw = h_last @ fc_w^T + fc_b --------
    gemm_bias<<<dim3((RAWN + 63) / 64, B_SZ / 128), 256>>>(
        nullptr, /*asel=*/2, fc_w, fc_b, nullptr, /*csel=*/1,
        B_SZ, RAWN, HID, /*mode=*/0);

    // -------- Sigma --------
    sigma_kernel<<<dim3(8, 8, B_SZ), 256>>>(out);
}

// round 2
// speedup vs baseline: 1.8814x; 1.8814x over previous
#include <cuda_runtime.h>
#include <math.h>
#include <stdint.h>

// Problem constants
#define B_SZ   256
#define T_SZ   64
#define IN_SZ  500
#define HID    512
#define G4     2048            // 4*HID
#define RAWN   16532           // 500*32 + 32 + 500
#define NA     500
#define NF     32

// ---------------- device scratch (static, no allocation) ----------------
__device__ float g_xg[(size_t)T_SZ * B_SZ * G4];      // input-transform (reused for both layers)
__device__ float g_hseq[(size_t)T_SZ * B_SZ * HID];   // layer-0 hidden sequence
__device__ float g_hA[B_SZ * HID];
__device__ float g_hB[B_SZ * HID];
__device__ float g_c[B_SZ * HID];
__device__ float g_raw[(size_t)B_SZ * RAWN];          // FC output

__device__ __forceinline__ float sigmf(float x) { return 1.f / (1.f + expf(-x)); }

__device__ __forceinline__ uint32_t f2tf32(float f) {
    uint32_t r;
    asm("cvt.rna.tf32.f32 %0, %1;" : "=r"(r) : "f"(f));
    return r;
}

__device__ __forceinline__ void mma_tf32(float* c, const uint32_t* a, const uint32_t* b) {
    asm volatile(
        "mma.sync.aligned.m16n8k8.row.col.f32.tf32.tf32.f32 "
        "{%0,%1,%2,%3}, {%4,%5,%6,%7}, {%8,%9}, {%0,%1,%2,%3};\n"
        : "+f"(c[0]), "+f"(c[1]), "+f"(c[2]), "+f"(c[3])
        : "r"(a[0]), "r"(a[1]), "r"(a[2]), "r"(a[3]), "r"(b[0]), "r"(b[1]));
}

// Shared memory: mainloop tiles (tf32 bits) union'd with C staging buffer.
union SmemT {
    struct { uint32_t A[2][64][36]; uint32_t B[2][64][36]; } ld;   // 36864 B
    float Cs[64][72];                                              // 18432 B
};

// ---------------- zero h/c ----------------
__global__ void zero_hc_kernel() {
    int i = blockIdx.x * 256 + threadIdx.x;   // 512 * 256 = 131072 = 256*512
    g_hA[i] = 0.f;
    g_c[i]  = 0.f;
}

// ---------------- tensor-core GEMM: C = A @ W^T + bias1 (+bias2) ----------------
// A: MxK fp32 row-major (M = gridDim.y*64), W: NxK fp32 row-major, C: MxN fp32.
// asel: 0=ext, 1=g_hseq, 2=g_hA.  csel: 0=g_xg, 1=g_raw.
// remap: out row (b*64+t) -> (t*256+b).
__global__ __launch_bounds__(128) void gemm_tc(
    const float* __restrict__ Aext, int asel,
    const float* __restrict__ W,
    const float* __restrict__ bias1, const float* __restrict__ bias2,
    int csel, int N, int K, int remap)
{
    __shared__ SmemT sm;

    const float* A = (asel == 0) ? Aext : (asel == 1 ? g_hseq : g_hA);
    float* C = csel ? g_raw : g_xg;

    const int tid  = threadIdx.x;
    const int lane = tid & 31;
    const int warp = tid >> 5;
    const int wm   = (warp >> 1) * 32;
    const int wn   = (warp & 1) * 32;
    const int gid  = lane >> 2;
    const int tig  = lane & 3;
    const int m0   = blockIdx.y * 64;
    const int n0   = blockIdx.x * 64;

    float c[2][4][4];
#pragma unroll
    for (int mt = 0; mt < 2; mt++)
#pragma unroll
        for (int nt = 0; nt < 4; nt++)
#pragma unroll
            for (int q = 0; q < 4; q++) c[mt][nt][q] = 0.f;

    const int ktiles = (K + 31) >> 5;

    // ---- load tile 0 directly ----
#pragma unroll
    for (int i = 0; i < 4; i++) {
        int s = tid + i * 128;
        int row = s >> 3, kq = s & 7;
        int kk = kq * 4;
        float4 va = make_float4(0, 0, 0, 0), vb = make_float4(0, 0, 0, 0);
        if (kk < K) {
            va = *(const float4*)&A[(size_t)(m0 + row) * K + kk];
            int wr = n0 + row;
            if (wr < N) vb = *(const float4*)&W[(size_t)wr * K + kk];
        }
        uint4 ua = {f2tf32(va.x), f2tf32(va.y), f2tf32(va.z), f2tf32(va.w)};
        uint4 ub = {f2tf32(vb.x), f2tf32(vb.y), f2tf32(vb.z), f2tf32(vb.w)};
        *(uint4*)&sm.ld.A[0][row][kq * 4] = ua;
        *(uint4*)&sm.ld.B[0][row][kq * 4] = ub;
    }
    __syncthreads();

    float4 pa[4], pb[4];
    for (int kt = 0; kt < ktiles; kt++) {
        const int buf = kt & 1;
        const bool pf = (kt + 1 < ktiles);
        const int k0n = (kt + 1) << 5;
        if (pf) {
#pragma unroll
            for (int i = 0; i < 4; i++) {
                int s = tid + i * 128;
                int row = s >> 3, kq = s & 7;
                int kk = k0n + kq * 4;
                pa[i] = make_float4(0, 0, 0, 0);
                pb[i] = make_float4(0, 0, 0, 0);
                if (kk < K) {
                    pa[i] = *(const float4*)&A[(size_t)(m0 + row) * K + kk];
                    int wr = n0 + row;
                    if (wr < N) pb[i] = *(const float4*)&W[(size_t)wr * K + kk];
                }
            }
        }
        // ---- compute on buf ----
#pragma unroll
        for (int kk8 = 0; kk8 < 4; kk8++) {
            uint32_t af[2][4];
#pragma unroll
            for (int mt = 0; mt < 2; mt++) {
                int r = wm + mt * 16 + gid;
                af[mt][0] = sm.ld.A[buf][r][kk8 * 8 + tig];
                af[mt][1] = sm.ld.A[buf][r + 8][kk8 * 8 + tig];
                af[mt][2] = sm.ld.A[buf][r][kk8 * 8 + tig + 4];
                af[mt][3] = sm.ld.A[buf][r + 8][kk8 * 8 + tig + 4];
            }
#pragma unroll
            for (int nt = 0; nt < 4; nt++) {
                uint32_t bf[2];
                int cn = wn + nt * 8 + gid;
                bf[0] = sm.ld.B[buf][cn][kk8 * 8 + tig];
                bf[1] = sm.ld.B[buf][cn][kk8 * 8 + tig + 4];
                mma_tf32(c[0][nt], af[0], bf);
                mma_tf32(c[1][nt], af[1], bf);
            }
        }
        if (pf) {
#pragma unroll
            for (int i = 0; i < 4; i++) {
                int s = tid + i * 128;
                int row = s >> 3, kq = s & 7;
                uint4 ua = {f2tf32(pa[i].x), f2tf32(pa[i].y), f2tf32(pa[i].z), f2tf32(pa[i].w)};
                uint4 ub = {f2tf32(pb[i].x), f2tf32(pb[i].y), f2tf32(pb[i].z), f2tf32(pb[i].w)};
                *(uint4*)&sm.ld.A[buf ^ 1][row][kq * 4] = ua;
                *(uint4*)&sm.ld.B[buf ^ 1][row][kq * 4] = ub;
            }
        }
        __syncthreads();
    }

    // ---- stage C to smem (aliases tile buffers; mainloop done) ----
#pragma unroll
    for (int mt = 0; mt < 2; mt++)
#pragma unroll
        for (int nt = 0; nt < 4; nt++) {
            int r  = wm + mt * 16 + gid;
            int cb = wn + nt * 8 + 2 * tig;
            sm.Cs[r][cb]     = c[mt][nt][0];
            sm.Cs[r][cb + 1] = c[mt][nt][1];
            sm.Cs[r + 8][cb]     = c[mt][nt][2];
            sm.Cs[r + 8][cb + 1] = c[mt][nt][3];
        }
    __syncthreads();

    // ---- coalesced output with bias ----
#pragma unroll
    for (int i = 0; i < 8; i++) {
        int s = tid + i * 128;
        int row = s >> 4, cq = s & 15;
        int colb = n0 + cq * 4;
        if (colb < N) {   // N % 4 == 0 in all uses
            float4 v = *(float4*)&sm.Cs[row][cq * 4];
            float4 b1 = *(const float4*)&bias1[colb];
            v.x += b1.x; v.y += b1.y; v.z += b1.z; v.w += b1.w;
            if (bias2) {
                float4 b2 = *(const float4*)&bias2[colb];
                v.x += b2.x; v.y += b2.y; v.z += b2.z; v.w += b2.w;
            }
            int m = m0 + row;
            int orow = remap ? ((m & 63) * 256 + (m >> 6)) : m;
            *(float4*)&C[(size_t)orow * N + colb] = v;
        }
    }
}

// ---------------- fused tensor-core LSTM step ----------------
// Block tile: 64 batch x 64 gate-cols (= 16 hidden units x 4 interleaved gates).
// grid (512/16=32, 256/64=4), 128 threads.
__global__ __launch_bounds__(128) void lstm_tc(
    int t, const float* __restrict__ w_hh, int layer)
{
    __shared__ SmemT sm;

    const float* xg   = g_xg + (size_t)t * B_SZ * G4;
    const float* h_in = (t & 1) ? g_hB : g_hA;
    float* h_out      = (t & 1) ? g_hA : g_hB;
    float* hseq       = (layer == 0) ? (g_hseq + (size_t)t * B_SZ * HID) : nullptr;

    const int tid  = threadIdx.x;
    const int lane = tid & 31;
    const int warp = tid >> 5;
    const int wm   = (warp >> 1) * 32;
    const int wn   = (warp & 1) * 32;
    const int gid  = lane >> 2;
    const int tig  = lane & 3;
    const int h0   = blockIdx.x * 16;
    const int m0   = blockIdx.y * 64;

    float c[2][4][4];
#pragma unroll
    for (int mt = 0; mt < 2; mt++)
#pragma unroll
        for (int nt = 0; nt < 4; nt++)
#pragma unroll
            for (int q = 0; q < 4; q++) c[mt][nt][q] = 0.f;

    const int ktiles = HID / 32;   // 16

    // ---- tile 0 ----
#pragma unroll
    for (int i = 0; i < 4; i++) {
        int s = tid + i * 128;
        int row = s >> 3, kq = s & 7;
        int kk = kq * 4;
        float4 va = *(const float4*)&h_in[(size_t)(m0 + row) * HID + kk];
        int wr = (row & 3) * HID + h0 + (row >> 2);   // interleaved gate mapping
        float4 vb = *(const float4*)&w_hh[(size_t)wr * HID + kk];
        uint4 ua = {f2tf32(va.x), f2tf32(va.y), f2tf32(va.z), f2tf32(va.w)};
        uint4 ub = {f2tf32(vb.x), f2tf32(vb.y), f2tf32(vb.z), f2tf32(vb.w)};
        *(uint4*)&sm.ld.A[0][row][kq * 4] = ua;
        *(uint4*)&sm.ld.B[0][row][kq * 4] = ub;
    }
    __syncthreads();

    float4 pa[4], pb[4];
    for (int kt = 0; kt < ktiles; kt++) {
        const int buf = kt & 1;
        const bool pf = (kt + 1 < ktiles);
        const int k0n = (kt + 1) << 5;
        if (pf) {
#pragma unroll
            for (int i = 0; i < 4; i++) {
                int s = tid + i * 128;
                int row = s >> 3, kq = s & 7;
                int kk = k0n + kq * 4;
                pa[i] = *(const float4*)&h_in[(size_t)(m0 + row) * HID + kk];
                int wr = (row & 3) * HID + h0 + (row >> 2);
                pb[i] = *(const float4*)&w_hh[(size_t)wr * HID + kk];
            }
        }
#pragma unroll
        for (int kk8 = 0; kk8 < 4; kk8++) {
            uint32_t af[2][4];
#pragma unroll
            for (int mt = 0; mt < 2; mt++) {
                int r = wm + mt * 16 + gid;
                af[mt][0] = sm.ld.A[buf][r][kk8 * 8 + tig];
                af[mt][1] = sm.ld.A[buf][r + 8][kk8 * 8 + tig];
                af[mt][2] = sm.ld.A[buf][r][kk8 * 8 + tig + 4];
                af[mt][3] = sm.ld.A[buf][r + 8][kk8 * 8 + tig + 4];
            }
#pragma unroll
            for (int nt = 0; nt < 4; nt++) {
                uint32_t bf[2];
                int cn = wn + nt * 8 + gid;
                bf[0] = sm.ld.B[buf][cn][kk8 * 8 + tig];
                bf[1] = sm.ld.B[buf][cn][kk8 * 8 + tig + 4];
                mma_tf32(c[0][nt], af[0], bf);
                mma_tf32(c[1][nt], af[1], bf);
            }
        }
        if (pf) {
#pragma unroll
            for (int i = 0; i < 4; i++) {
                int s = tid + i * 128;
                int row = s >> 3, kq = s & 7;
                uint4 ua = {f2tf32(pa[i].x), f2tf32(pa[i].y), f2tf32(pa[i].z), f2tf32(pa[i].w)};
                uint4 ub = {f2tf32(pb[i].x), f2tf32(pb[i].y), f2tf32(pb[i].z), f2tf32(pb[i].w)};
                *(uint4*)&sm.ld.A[buf ^ 1][row][kq * 4] = ua;
                *(uint4*)&sm.ld.B[buf ^ 1][row][kq * 4] = ub;
            }
        }
        __syncthreads();
    }

    // ---- stage gate tile ----
#pragma unroll
    for (int mt = 0; mt < 2; mt++)
#pragma unroll
        for (int nt = 0; nt < 4; nt++) {
            int r  = wm + mt * 16 + gid;
            int cb = wn + nt * 8 + 2 * tig;
            sm.Cs[r][cb]     = c[mt][nt][0];
            sm.Cs[r][cb + 1] = c[mt][nt][1];
            sm.Cs[r + 8][cb]     = c[mt][nt][2];
            sm.Cs[r + 8][cb + 1] = c[mt][nt][3];
        }
    __syncthreads();

    // ---- cell update: 64 batch x 16 hidden cells, 8 per thread ----
#pragma unroll
    for (int i = 0; i < 8; i++) {
        int s = tid + i * 128;
        int bl = s >> 4, j = s & 15;
        int b = m0 + bl;
        int h = h0 + j;
        const float* xgb = xg + (size_t)b * G4;
        float gi = sm.Cs[bl][j * 4 + 0] + xgb[h];
        float gf = sm.Cs[bl][j * 4 + 1] + xgb[HID + h];
        float gg = sm.Cs[bl][j * 4 + 2] + xgb[2 * HID + h];
        float go = sm.Cs[bl][j * 4 + 3] + xgb[3 * HID + h];
        int ci = b * HID + h;
        float cn = sigmf(gf) * g_c[ci] + sigmf(gi) * tanhf(gg);
        float hn = sigmf(go) * tanhf(cn);
        g_c[ci] = cn;
        h_out[ci] = hn;
        if (hseq) hseq[ci] = hn;
    }
}

// ---------------- Sigma = (L*fv) @ L^T + diag(idio) ----------------
__global__ __launch_bounds__(256) void sigma_kernel(float* __restrict__ out)
{
    __shared__ float fvs[32];
    __shared__ float Ln[32][64];
    __shared__ float Lm[32][64];

    const int b  = blockIdx.z;
    const int n0 = blockIdx.y * 64;
    const int m0 = blockIdx.x * 64;
    const int tid = threadIdx.x;
    const int tx = tid & 15;
    const int ty = tid >> 4;
    const float* rb = g_raw + (size_t)b * RAWN;

    if (tid < 32) fvs[tid] = expf(rb[NA * NF + tid]);
    __syncthreads();

#pragma unroll
    for (int i = 0; i < 8; i++) {
        int idx = tid + i * 256;
        int nl = idx >> 5, f = idx & 31;
        int n = n0 + nl;
        float v = (n < NA) ? rb[n * NF + f] : 0.f;
        Ln[f][nl] = v * fvs[f];
        int m = m0 + nl;
        float w = (m < NA) ? rb[m * NF + f] : 0.f;
        Lm[f][nl] = w;
    }
    __syncthreads();

    float acc[4][4];
#pragma unroll
    for (int r = 0; r < 4; r++)
#pragma unroll
        for (int cc = 0; cc < 4; cc++) acc[r][cc] = 0.f;

#pragma unroll
    for (int f = 0; f < 32; f++) {
        float4 a = *reinterpret_cast<const float4*>(&Ln[f][ty * 4]);
        float4 bb = *reinterpret_cast<const float4*>(&Lm[f][tx * 4]);
        float av[4] = {a.x, a.y, a.z, a.w};
        float bv[4] = {bb.x, bb.y, bb.z, bb.w};
#pragma unroll
        for (int r = 0; r < 4; r++)
#pragma unroll
            for (int cc = 0; cc < 4; cc++)
                acc[r][cc] = fmaf(av[r], bv[cc], acc[r][cc]);
    }

    const int mBase = m0 + tx * 4;
    if (mBase < NA) {
#pragma unroll
        for (int r = 0; r < 4; r++) {
            int n = n0 + ty * 4 + r;
            if (n >= NA) continue;
            float o[4] = {acc[r][0], acc[r][1], acc[r][2], acc[r][3]};
            int d = n - mBase;
            if (d >= 0 && d < 4) o[d] += expf(rb[NA * NF + NF + n]);
            float4 ov = {o[0], o[1], o[2], o[3]};
            *reinterpret_cast<float4*>(&out[(size_t)b * NA * NA + (size_t)n * NA + mBase]) = ov;
        }
    }
}

// ---------------- launch ----------------
extern "C" void kernel_launch(void* const* d_in, const int* in_sizes, int n_in,
                              void* d_out, int out_size)
{
    const float* x     = (const float*)d_in[0];
    const float* w_ih0 = (const float*)d_in[1];
    const float* w_hh0 = (const float*)d_in[2];
    const float* b_ih0 = (const float*)d_in[3];
    const float* b_hh0 = (const float*)d_in[4];
    const float* w_ih1 = (const float*)d_in[5];
    const float* w_hh1 = (const float*)d_in[6];
    const float* b_ih1 = (const float*)d_in[7];
    const float* b_hh1 = (const float*)d_in[8];
    const float* fc_w  = (const float*)d_in[9];
    const float* fc_b  = (const float*)d_in[10];
    float* out = (float*)d_out;

    // -------- layer 0 --------
    zero_hc_kernel<<<512, 256>>>();
    // xg0[t][b][:] = x[b][t][:] @ w_ih0^T + b_ih0 + b_hh0 (remap rows)
    gemm_tc<<<dim3(G4 / 64, (B_SZ * T_SZ) / 64), 128>>>(
        x, /*asel=*/0, w_ih0, b_ih0, b_hh0, /*csel=*/0,
        G4, IN_SZ, /*remap=*/1);
    for (int t = 0; t < T_SZ; t++)
        lstm_tc<<<dim3(HID / 16, B_SZ / 64), 128>>>(t, w_hh0, /*layer=*/0);

    // -------- layer 1 --------
    zero_hc_kernel<<<512, 256>>>();
    gemm_tc<<<dim3(G4 / 64, (B_SZ * T_SZ) / 64), 128>>>(
        nullptr, /*asel=*/1, w_ih1, b_ih1, b_hh1, /*csel=*/0,
        G4, HID, /*remap=*/0);
    for (int t = 0; t < T_SZ; t++)
        lstm_tc<<<dim3(HID / 16, B_SZ / 64), 128>>>(t, w_hh1, /*layer=*/1);
    // final h (t=63, odd) lives in g_hA

    // -------- FC: raw = h_last @ fc_w^T + fc_b --------
    gemm_tc<<<dim3((RAWN + 63) / 64, B_SZ / 64), 128>>>(
        nullptr, /*asel=*/2, fc_w, fc_b, nullptr, /*csel=*/1,
        RAWN, HID, /*remap=*/0);

    // -------- Sigma --------
    sigma_kernel<<<dim3(8, 8, B_SZ), 256>>>(out);
}

// round 3
// speedup vs baseline: 2.1423x; 1.1387x over previous
#include <cuda_runtime.h>
#include <math.h>
#include <stdint.h>

// Problem constants
#define B_SZ   256
#define T_SZ   64
#define IN_SZ  500
#define HID    512
#define G4     2048            // 4*HID
#define RAWN   16532           // 500*32 + 32 + 500
#define NA     500
#define NF     32
#define GRIDN  128             // persistent grid size (<= SM count, 1 block/SM)

// ---------------- device scratch (static, no allocation) ----------------
__device__ float g_xg[(size_t)T_SZ * B_SZ * G4];      // input-transform (reused for both layers)
__device__ float g_hseq[(size_t)T_SZ * B_SZ * HID];   // layer-0 hidden sequence
__device__ float g_hA[B_SZ * HID];
__device__ float g_hB[B_SZ * HID];
__device__ float g_raw[(size_t)B_SZ * RAWN];          // FC output
__device__ unsigned long long g_flags[GRIDN];         // grid barrier flags (monotone, zero-init)

__device__ __forceinline__ float sigmf(float x) { return 1.f / (1.f + expf(-x)); }

__device__ __forceinline__ uint32_t f2tf32(float f) {
    uint32_t r;
    asm("cvt.rna.tf32.f32 %0, %1;" : "=r"(r) : "f"(f));
    return r;
}

__device__ __forceinline__ void mma_tf32(float* c, const uint32_t* a, const uint32_t* b) {
    asm volatile(
        "mma.sync.aligned.m16n8k8.row.col.f32.tf32.tf32.f32 "
        "{%0,%1,%2,%3}, {%4,%5,%6,%7}, {%8,%9}, {%0,%1,%2,%3};\n"
        : "+f"(c[0]), "+f"(c[1]), "+f"(c[2]), "+f"(c[3])
        : "r"(a[0]), "r"(a[1]), "r"(a[2]), "r"(a[3]), "r"(b[0]), "r"(b[1]));
}

// ================= persistent fused LSTM layer =================
// grid = 128 blocks (32 hid-chunks x 4 batch-chunks), 256 threads (8 warps).
// Block owns: weight slice [64 gate-cols x 512] in smem (tf32), and the cell
// state c for its 64(batch) x 16(hidden) cells in registers (4 per thread).
// Per step: GEMM  h_in[64x512] @ Wslice^T -> gates[64x64], fused cell update,
// then a distributed-flag grid barrier.
//
// smem word layout (uint32):
//   Wsm : [64][516]   offset 0          (33024 words)
//   Asm0: [64][68]    offset 33024      (4352)
//   Asm1: [64][68]    offset 37376      (4352)
//   Cs  : [64][68] f32 offset 41728     (4352)
#define W_STR 516
#define A_STR 68
#define SM_WORDS (33024 + 4352 + 4352 + 4352)   // 46080 words = 184320 B

__global__ __launch_bounds__(256, 1) void lstm_persist(
    const float* __restrict__ w_hh, int layer)
{
    extern __shared__ uint32_t smraw[];
    uint32_t* Wsm  = smraw;
    uint32_t* Asm0 = smraw + 33024;
    uint32_t* Asm1 = smraw + 37376;
    float*    Cs   = (float*)(smraw + 41728);

    const int tid  = threadIdx.x;
    const int lane = tid & 31;
    const int warp = tid >> 5;
    const int wm   = (warp >> 1) * 16;    // 4 warps along M
    const int wn   = (warp & 1) * 32;     // 2 warps along N
    const int gid  = lane >> 2;
    const int tig  = lane & 3;
    const int nchunk = blockIdx.x & 31;
    const int bchunk = blockIdx.x >> 5;
    const int h0 = nchunk * 16;
    const int m0 = bchunk * 64;

    // ---- load weight slice to smem once (gate-interleaved cols) ----
    // smem row n (0..63) -> w_hh row (n&3)*HID + h0 + (n>>2)
#pragma unroll
    for (int i = 0; i < 32; i++) {
        int s   = tid + (i << 8);          // 0..8191 float4 units
        int row = s >> 7;                  // 0..63
        int kq  = s & 127;                 // float4 index within 512
        int wr  = ((row & 3) << 9) + h0 + (row >> 2);
        float4 v = *(const float4*)&w_hh[(size_t)wr * HID + (kq << 2)];
        uint4 u = { f2tf32(v.x), f2tf32(v.y), f2tf32(v.z), f2tf32(v.w) };
        *(uint4*)&Wsm[row * W_STR + (kq << 2)] = u;
    }

    // barrier base: this block's own flag (only this block writes it)
    const unsigned long long barBase = *(volatile unsigned long long*)&g_flags[blockIdx.x];

    // cell state in registers: thread owns cells (bl = tid>>4 + i*16, j = tid&15)
    float creg[4] = {0.f, 0.f, 0.f, 0.f};
    const int jj  = tid & 15;
    const int bl0 = tid >> 4;

    __syncthreads();

    for (int t = 0; t < T_SZ; t++) {
        const float* h_in = (t & 1) ? g_hB : g_hA;
        float* h_out      = (t & 1) ? g_hA : g_hB;

        if (t > 0) {
            float c[4][4];
#pragma unroll
            for (int nt = 0; nt < 4; nt++)
#pragma unroll
                for (int q = 0; q < 4; q++) c[nt][q] = 0.f;

            // ---- K tile 0 ----
#pragma unroll
            for (int i = 0; i < 4; i++) {
                int s = tid + (i << 8);
                int row = s >> 4, kq = s & 15;
                float4 v = __ldcg((const float4*)&h_in[(size_t)(m0 + row) * HID + (kq << 2)]);
                uint4 u = { f2tf32(v.x), f2tf32(v.y), f2tf32(v.z), f2tf32(v.w) };
                *(uint4*)&Asm0[row * A_STR + (kq << 2)] = u;
            }
            __syncthreads();

            float4 pf[4];
#pragma unroll 1
            for (int kt = 0; kt < 8; kt++) {
                uint32_t* Ab = (kt & 1) ? Asm1 : Asm0;
                const bool pfl = (kt < 7);
                if (pfl) {
#pragma unroll
                    for (int i = 0; i < 4; i++) {
                        int s = tid + (i << 8);
                        int row = s >> 4, kq = s & 15;
                        pf[i] = __ldcg((const float4*)&h_in[
                            (size_t)(m0 + row) * HID + ((kt + 1) << 6) + (kq << 2)]);
                    }
                }
#pragma unroll
                for (int k8 = 0; k8 < 8; k8++) {
                    const int kc = k8 * 8 + tig;
                    uint32_t af[4];
                    af[0] = Ab[(wm + gid)     * A_STR + kc];
                    af[1] = Ab[(wm + gid + 8) * A_STR + kc];
                    af[2] = Ab[(wm + gid)     * A_STR + kc + 4];
                    af[3] = Ab[(wm + gid + 8) * A_STR + kc + 4];
                    const int kw = (kt << 6) + kc;
#pragma unroll
                    for (int nt = 0; nt < 4; nt++) {
                        int cn = wn + nt * 8 + gid;
                        uint32_t bf[2];
                        bf[0] = Wsm[cn * W_STR + kw];
                        bf[1] = Wsm[cn * W_STR + kw + 4];
                        mma_tf32(c[nt], af, bf);
                    }
                }
                if (pfl) {
                    uint32_t* An = (kt & 1) ? Asm0 : Asm1;
#pragma unroll
                    for (int i = 0; i < 4; i++) {
                        int s = tid + (i << 8);
                        int row = s >> 4, kq = s & 15;
                        uint4 u = { f2tf32(pf[i].x), f2tf32(pf[i].y),
                                    f2tf32(pf[i].z), f2tf32(pf[i].w) };
                        *(uint4*)&An[row * A_STR + (kq << 2)] = u;
                    }
                }
                __syncthreads();
            }

            // ---- stage gates to smem ----
#pragma unroll
            for (int nt = 0; nt < 4; nt++) {
                int r  = wm + gid;
                int cb = wn + nt * 8 + 2 * tig;
                Cs[r * A_STR + cb]           = c[nt][0];
                Cs[r * A_STR + cb + 1]       = c[nt][1];
                Cs[(r + 8) * A_STR + cb]     = c[nt][2];
                Cs[(r + 8) * A_STR + cb + 1] = c[nt][3];
            }
            __syncthreads();
        }

        // ---- fused cell update (register-resident c) ----
        const float* xgt = g_xg + (size_t)t * B_SZ * G4;
        const int h = h0 + jj;
#pragma unroll
        for (int i = 0; i < 4; i++) {
            int bl = bl0 + i * 16;
            int b  = m0 + bl;
            const float* xgb = xgt + (size_t)b * G4;
            float gi, gf, gg, go;
            if (t > 0) {
                float4 gv = *(float4*)&Cs[bl * A_STR + jj * 4];
                gi = gv.x; gf = gv.y; gg = gv.z; go = gv.w;
            } else {
                gi = gf = gg = go = 0.f;
            }
            gi += xgb[h];
            gf += xgb[HID + h];
            gg += xgb[2 * HID + h];
            go += xgb[3 * HID + h];
            float cn = sigmf(gf) * creg[i] + sigmf(gi) * tanhf(gg);
            float hn = sigmf(go) * tanhf(cn);
            creg[i] = cn;
            h_out[b * HID + h] = hn;
            if (layer == 0) g_hseq[(size_t)t * B_SZ * HID + b * HID + h] = hn;
        }

        // ---- grid barrier (distributed flags, monotone across replays) ----
        if (t < T_SZ - 1) {
            __threadfence();
            __syncthreads();
            const unsigned long long tgt = barBase + (unsigned long long)(t + 1);
            if (tid == 0)
                *(volatile unsigned long long*)&g_flags[blockIdx.x] = tgt;
            if (tid < GRIDN) {
                while (*(volatile unsigned long long*)&g_flags[tid] < tgt)
                    __nanosleep(64);
            }
            __syncthreads();
        }
    }
}

// ---------------- tensor-core GEMM: C = A @ W^T + bias1 (+bias2) ----------------
union SmemT {
    struct { uint32_t A[2][64][36]; uint32_t B[2][64][36]; } ld;
    float Cs[64][72];
};

__global__ __launch_bounds__(128) void gemm_tc(
    const float* __restrict__ Aext, int asel,
    const float* __restrict__ W,
    const float* __restrict__ bias1, const float* __restrict__ bias2,
    int csel, int N, int K, int remap)
{
    __shared__ SmemT sm;

    const float* A = (asel == 0) ? Aext : (asel == 1 ? g_hseq : g_hA);
    float* C = csel ? g_raw : g_xg;

    const int tid  = threadIdx.x;
    const int lane = tid & 31;
    const int warp = tid >> 5;
    const int wm   = (warp >> 1) * 32;
    const int wn   = (warp & 1) * 32;
    const int gid  = lane >> 2;
    const int tig  = lane & 3;
    const int m0   = blockIdx.y * 64;
    const int n0   = blockIdx.x * 64;

    float c[2][4][4];
#pragma unroll
    for (int mt = 0; mt < 2; mt++)
#pragma unroll
        for (int nt = 0; nt < 4; nt++)
#pragma unroll
            for (int q = 0; q < 4; q++) c[mt][nt][q] = 0.f;

    const int ktiles = (K + 31) >> 5;

#pragma unroll
    for (int i = 0; i < 4; i++) {
        int s = tid + i * 128;
        int row = s >> 3, kq = s & 7;
        int kk = kq * 4;
        float4 va = make_float4(0, 0, 0, 0), vb = make_float4(0, 0, 0, 0);
        if (kk < K) {
            va = *(const float4*)&A[(size_t)(m0 + row) * K + kk];
            int wr = n0 + row;
            if (wr < N) vb = *(const float4*)&W[(size_t)wr * K + kk];
        }
        uint4 ua = {f2tf32(va.x), f2tf32(va.y), f2tf32(va.z), f2tf32(va.w)};
        uint4 ub = {f2tf32(vb.x), f2tf32(vb.y), f2tf32(vb.z), f2tf32(vb.w)};
        *(uint4*)&sm.ld.A[0][row][kq * 4] = ua;
        *(uint4*)&sm.ld.B[0][row][kq * 4] = ub;
    }
    __syncthreads();

    float4 pa[4], pb[4];
    for (int kt = 0; kt < ktiles; kt++) {
        const int buf = kt & 1;
        const bool pf = (kt + 1 < ktiles);
        const int k0n = (kt + 1) << 5;
        if (pf) {
#pragma unroll
            for (int i = 0; i < 4; i++) {
                int s = tid + i * 128;
                int row = s >> 3, kq = s & 7;
                int kk = k0n + kq * 4;
                pa[i] = make_float4(0, 0, 0, 0);
                pb[i] = make_float4(0, 0, 0, 0);
                if (kk < K) {
                    pa[i] = *(const float4*)&A[(size_t)(m0 + row) * K + kk];
                    int wr = n0 + row;
                    if (wr < N) pb[i] = *(const float4*)&W[(size_t)wr * K + kk];
                }
            }
        }
#pragma unroll
        for (int kk8 = 0; kk8 < 4; kk8++) {
            uint32_t af[2][4];
#pragma unroll
            for (int mt = 0; mt < 2; mt++) {
                int r = wm + mt * 16 + gid;
                af[mt][0] = sm.ld.A[buf][r][kk8 * 8 + tig];
                af[mt][1] = sm.ld.A[buf][r + 8][kk8 * 8 + tig];
                af[mt][2] = sm.ld.A[buf][r][kk8 * 8 + tig + 4];
                af[mt][3] = sm.ld.A[buf][r + 8][kk8 * 8 + tig + 4];
            }
#pragma unroll
            for (int nt = 0; nt < 4; nt++) {
                uint32_t bf[2];
                int cn = wn + nt * 8 + gid;
                bf[0] = sm.ld.B[buf][cn][kk8 * 8 + tig];
                bf[1] = sm.ld.B[buf][cn][kk8 * 8 + tig + 4];
                mma_tf32(c[0][nt], af[0], bf);
                mma_tf32(c[1][nt], af[1], bf);
            }
        }
        if (pf) {
#pragma unroll
            for (int i = 0; i < 4; i++) {
                int s = tid + i * 128;
                int row = s >> 3, kq = s & 7;
                uint4 ua = {f2tf32(pa[i].x), f2tf32(pa[i].y), f2tf32(pa[i].z), f2tf32(pa[i].w)};
                uint4 ub = {f2tf32(pb[i].x), f2tf32(pb[i].y), f2tf32(pb[i].z), f2tf32(pb[i].w)};
                *(uint4*)&sm.ld.A[buf ^ 1][row][kq * 4] = ua;
                *(uint4*)&sm.ld.B[buf ^ 1][row][kq * 4] = ub;
            }
        }
        __syncthreads();
    }

#pragma unroll
    for (int mt = 0; mt < 2; mt++)
#pragma unroll
        for (int nt = 0; nt < 4; nt++) {
            int r  = wm + mt * 16 + gid;
            int cb = wn + nt * 8 + 2 * tig;
            sm.Cs[r][cb]     = c[mt][nt][0];
            sm.Cs[r][cb + 1] = c[mt][nt][1];
            sm.Cs[r + 8][cb]     = c[mt][nt][2];
            sm.Cs[r + 8][cb + 1] = c[mt][nt][3];
        }
    __syncthreads();

#pragma unroll
    for (int i = 0; i < 8; i++) {
        int s = tid + i * 128;
        int row = s >> 4, cq = s & 15;
        int colb = n0 + cq * 4;
        if (colb < N) {
            float4 v = *(float4*)&sm.Cs[row][cq * 4];
            float4 b1 = *(const float4*)&bias1[colb];
            v.x += b1.x; v.y += b1.y; v.z += b1.z; v.w += b1.w;
            if (bias2) {
                float4 b2 = *(const float4*)&bias2[colb];
                v.x += b2.x; v.y += b2.y; v.z += b2.z; v.w += b2.w;
            }
            int m = m0 + row;
            int orow = remap ? ((m & 63) * 256 + (m >> 6)) : m;
            *(float4*)&C[(size_t)orow * N + colb] = v;
        }
    }
}

// ---------------- Sigma = (L*fv) @ L^T + diag(idio) ----------------
__global__ __launch_bounds__(256) void sigma_kernel(float* __restrict__ out)
{
    __shared__ float fvs[32];
    __shared__ float Ln[32][64];
    __shared__ float Lm[32][64];

    const int b  = blockIdx.z;
    const int n0 = blockIdx.y * 64;
    const int m0 = blockIdx.x * 64;
    const int tid = threadIdx.x;
    const int tx = tid & 15;
    const int ty = tid >> 4;
    const float* rb = g_raw + (size_t)b * RAWN;

    if (tid < 32) fvs[tid] = expf(rb[NA * NF + tid]);
    __syncthreads();

#pragma unroll
    for (int i = 0; i < 8; i++) {
        int idx = tid + i * 256;
        int nl = idx >> 5, f = idx & 31;
        int n = n0 + nl;
        float v = (n < NA) ? rb[n * NF + f] : 0.f;
        Ln[f][nl] = v * fvs[f];
        int m = m0 + nl;
        float w = (m < NA) ? rb[m * NF + f] : 0.f;
        Lm[f][nl] = w;
    }
    __syncthreads();

    float acc[4][4];
#pragma unroll
    for (int r = 0; r < 4; r++)
#pragma unroll
        for (int cc = 0; cc < 4; cc++) acc[r][cc] = 0.f;

#pragma unroll
    for (int f = 0; f < 32; f++) {
        float4 a = *reinterpret_cast<const float4*>(&Ln[f][ty * 4]);
        float4 bb = *reinterpret_cast<const float4*>(&Lm[f][tx * 4]);
        float av[4] = {a.x, a.y, a.z, a.w};
        float bv[4] = {bb.x, bb.y, bb.z, bb.w};
#pragma unroll
        for (int r = 0; r < 4; r++)
#pragma unroll
            for (int cc = 0; cc < 4; cc++)
                acc[r][cc] = fmaf(av[r], bv[cc], acc[r][cc]);
    }

    const int mBase = m0 + tx * 4;
    if (mBase < NA) {
#pragma unroll
        for (int r = 0; r < 4; r++) {
            int n = n0 + ty * 4 + r;
            if (n >= NA) continue;
            float o[4] = {acc[r][0], acc[r][1], acc[r][2], acc[r][3]};
            int d = n - mBase;
            if (d >= 0 && d < 4) o[d] += expf(rb[NA * NF + NF + n]);
            float4 ov = {o[0], o[1], o[2], o[3]};
            *reinterpret_cast<float4*>(&out[(size_t)b * NA * NA + (size_t)n * NA + mBase]) = ov;
        }
    }
}

// ---------------- launch ----------------
extern "C" void kernel_launch(void* const* d_in, const int* in_sizes, int n_in,
                              void* d_out, int out_size)
{
    const float* x     = (const float*)d_in[0];
    const float* w_ih0 = (const float*)d_in[1];
    const float* w_hh0 = (const float*)d_in[2];
    const float* b_ih0 = (const float*)d_in[3];
    const float* b_hh0 = (const float*)d_in[4];
    const float* w_ih1 = (const float*)d_in[5];
    const float* w_hh1 = (const float*)d_in[6];
    const float* b_ih1 = (const float*)d_in[7];
    const float* b_hh1 = (const float*)d_in[8];
    const float* fc_w  = (const float*)d_in[9];
    const float* fc_b  = (const float*)d_in[10];
    float* out = (float*)d_out;

    static bool attr_done = false;
    if (!attr_done) {
        cudaFuncSetAttribute(lstm_persist,
            cudaFuncAttributeMaxDynamicSharedMemorySize, SM_WORDS * 4);
        attr_done = true;
    }

    // -------- layer 0 --------
    gemm_tc<<<dim3(G4 / 64, (B_SZ * T_SZ) / 64), 128>>>(
        x, /*asel=*/0, w_ih0, b_ih0, b_hh0, /*csel=*/0,
        G4, IN_SZ, /*remap=*/1);
    lstm_persist<<<GRIDN, 256, SM_WORDS * 4>>>(w_hh0, /*layer=*/0);

    // -------- layer 1 --------
    gemm_tc<<<dim3(G4 / 64, (B_SZ * T_SZ) / 64), 128>>>(
        nullptr, /*asel=*/1, w_ih1, b_ih1, b_hh1, /*csel=*/0,
        G4, HID, /*remap=*/0);
    lstm_persist<<<GRIDN, 256, SM_WORDS * 4>>>(w_hh1, /*layer=*/1);
    // final h (t=63, odd) lives in g_hA

    // -------- FC: raw = h_last @ fc_w^T + fc_b --------
    gemm_tc<<<dim3((RAWN + 63) / 64, B_SZ / 64), 128>>>(
        nullptr, /*asel=*/2, fc_w, fc_b, nullptr, /*csel=*/1,
        RAWN, HID, /*remap=*/0);

    // -------- Sigma --------
    sigma_kernel<<<dim3(8, 8, B_SZ), 256>>>(out);
}